// round 16
// baseline (speedup 1.0000x reference)
#include <cuda_runtime.h>
#include <math.h>

#define EMB 1024
#define HID 1024
#define SEQ 2048
#define NEMO 16
#define LABELS 7
#define G4 (4*HID)

#define NB 128        // blocks in sequential kernel (<= 148 SMs -> co-resident)
#define JPB (HID/NB)  // 8 hidden units per block (= warps per block)
#define TPB 256

#define SPIN_SWEEP_LIMIT 4000000u  // ~1s of sweeps; only hit on genuine hang

// ---------------- static device scratch (no allocations allowed) ----------------
struct SeqState {
    float h[2][HID];     // double-buffered hidden state
};

__device__ float g_C [SEQ * EMB];       // relu(comb) per step       (8 MB)
__device__ float g_G [SEQ * G4];        // W_ih @ C + b_ih + b_hh    (32 MB)
__device__ float g_const2[EMB];         // We @ emoji_ave + comb_b
__device__ SeqState g_st;
// Per-block arrival flags (DISTINCT addresses -> no L2 atomic-ALU
// serialization; the old single shared counter cost ~128*27 cyc/step).
// Monotonic values (step+1), so no reset between steps and no ABA.
__device__ __align__(512) unsigned g_flags[NB];

// ---------------- fused prep kernel (launch #1) ----------------
// 128 blocks x 256 threads. Every block: emoji_ave -> smem, then const2 for
// its 8 comb_W rows (warp per row). Block 0 additionally zeroes the flags
// and both h buffers (k_seq comes later in stream order, also on graph replay).
__global__ __launch_bounds__(TPB) void k_prep(const int* __restrict__ eids,
                                              const float* __restrict__ eemb,
                                              const float* __restrict__ combW,
                                              const float* __restrict__ combB)
{
    __shared__ float esh[EMB];
    const int tid = threadIdx.x;
    const int warp = tid >> 5, lane = tid & 31;

    // emoji_ave into smem (redundant per block; tiny, L2-cached)
    for (int e = tid; e < EMB; e += TPB) {
        float s = 0.f;
        #pragma unroll
        for (int n = 0; n < NEMO; n++)
            s += eemb[(size_t)eids[n] * EMB + e];
        esh[e] = s * (1.0f / NEMO);
    }

    if (blockIdx.x == 0) {
        if (tid < NB) g_flags[tid] = 0u;
        float* h = &g_st.h[0][0];
        for (int i = tid; i < 2 * HID; i += TPB) h[i] = 0.f;
    }
    __syncthreads();

    // const2[row] = dot(comb_W[row, EMB:2EMB], emoji_ave) + comb_b[row]
    int row = blockIdx.x * 8 + warp;
    const float* wr = combW + (size_t)row * (2 * EMB) + EMB;
    float s = 0.f;
    for (int k = lane; k < EMB; k += 32) s += wr[k] * esh[k];
    #pragma unroll
    for (int off = 16; off; off >>= 1) s += __shfl_xor_sync(0xffffffffu, s, off);
    if (lane == 0) g_const2[row] = s + combB[row];
}

// ---------------- SIMT SGEMM:  C[M,N] = A[M,K] @ B[N,K]^T + bias(+bias2) (opt relu) ----
// 128x128 tile, TK=16, 256 threads, 8x8 per thread, double-buffered smem.
// If ids != nullptr, A row m is A[ids[m]] (fused embedding gather).
__global__ __launch_bounds__(256) void sgemm_nt(
    const float* __restrict__ A, int lda, const int* __restrict__ ids,
    const float* __restrict__ B, int ldb,
    const float* __restrict__ bias, const float* __restrict__ bias2,
    float* __restrict__ Cc, int ldc,
    int K, int relu)
{
    __shared__ float As[2][16][128];
    __shared__ float Bs[2][16][128];

    const int tid = threadIdx.x;
    const int m0 = blockIdx.y * 128;
    const int n0 = blockIdx.x * 128;
    const int tx = tid & 15;    // n micro-tile index
    const int ty = tid >> 4;    // m micro-tile index
    const int lr = tid >> 2;    // 0..63: tile row for loads
    const int lq = tid & 3;     // k-quad for loads

    const float* aptr[2];
    const float* bptr[2];
    #pragma unroll
    for (int s = 0; s < 2; s++) {
        int r = lr + s * 64;
        int am = ids ? ids[m0 + r] : (m0 + r);
        aptr[s] = A + (size_t)am * lda + lq * 4;
        bptr[s] = B + (size_t)(n0 + r) * ldb + lq * 4;
    }

    float4 ra[2], rb[2];

    float acc[8][8];
    #pragma unroll
    for (int r = 0; r < 8; r++)
        #pragma unroll
        for (int c = 0; c < 8; c++) acc[r][c] = 0.f;

    // prologue: tile 0 -> buf 0
    #pragma unroll
    for (int s = 0; s < 2; s++) { ra[s] = *(const float4*)(aptr[s]); rb[s] = *(const float4*)(bptr[s]); }
    #pragma unroll
    for (int s = 0; s < 2; s++) {
        int r = lr + s * 64;
        As[0][lq*4+0][r] = ra[s].x; As[0][lq*4+1][r] = ra[s].y;
        As[0][lq*4+2][r] = ra[s].z; As[0][lq*4+3][r] = ra[s].w;
        Bs[0][lq*4+0][r] = rb[s].x; Bs[0][lq*4+1][r] = rb[s].y;
        Bs[0][lq*4+2][r] = rb[s].z; Bs[0][lq*4+3][r] = rb[s].w;
    }
    __syncthreads();

    int buf = 0;
    for (int k0 = 16; k0 <= K; k0 += 16) {
        if (k0 < K) {
            #pragma unroll
            for (int s = 0; s < 2; s++) {
                ra[s] = *(const float4*)(aptr[s] + k0);
                rb[s] = *(const float4*)(bptr[s] + k0);
            }
        }

        #pragma unroll
        for (int k = 0; k < 16; k++) {
            float4 a0 = *(const float4*)&As[buf][k][ty * 8];
            float4 a1 = *(const float4*)&As[buf][k][ty * 8 + 4];
            float4 b0 = *(const float4*)&Bs[buf][k][tx * 8];
            float4 b1 = *(const float4*)&Bs[buf][k][tx * 8 + 4];
            float a[8] = {a0.x, a0.y, a0.z, a0.w, a1.x, a1.y, a1.z, a1.w};
            float b[8] = {b0.x, b0.y, b0.z, b0.w, b1.x, b1.y, b1.z, b1.w};
            #pragma unroll
            for (int r = 0; r < 8; r++)
                #pragma unroll
                for (int c = 0; c < 8; c++)
                    acc[r][c] += a[r] * b[c];
        }

        if (k0 < K) {
            int nb = buf ^ 1;
            #pragma unroll
            for (int s = 0; s < 2; s++) {
                int r = lr + s * 64;
                As[nb][lq*4+0][r] = ra[s].x; As[nb][lq*4+1][r] = ra[s].y;
                As[nb][lq*4+2][r] = ra[s].z; As[nb][lq*4+3][r] = ra[s].w;
                Bs[nb][lq*4+0][r] = rb[s].x; Bs[nb][lq*4+1][r] = rb[s].y;
                Bs[nb][lq*4+2][r] = rb[s].z; Bs[nb][lq*4+3][r] = rb[s].w;
            }
            __syncthreads();
            buf = nb;
        }
    }

    #pragma unroll
    for (int r = 0; r < 8; r++) {
        int m = m0 + ty * 8 + r;
        float* cp = Cc + (size_t)m * ldc + n0 + tx * 8;
        #pragma unroll
        for (int c = 0; c < 8; c++) {
            int n = n0 + tx * 8 + c;
            float v = acc[r][c] + bias[n];
            if (bias2) v += bias2[n];
            if (relu) v = fmaxf(v, 0.f);
            cp[c] = v;
        }
    }
}

// ---------------- persistent sequential LSTM kernel ----------------
// 128 blocks x 256 threads (8 warps). Warp-per-unit layout (R15, passed):
// warp w owns all four gate rows of hidden unit u = b*8+w, register-resident.
// Grid barrier, R5 SHAPE (one spinner = tid0; arrival after block-wide
// __syncthreads; fence before arrival, fence after spin) but the arrival
// primitive is a plain st.global.cg to a per-block DISTINCT flag address,
// and the spin is a batched sweep over all 128 flags (ld.global.cg.v4).
// This removes the measured ~3.5K cyc/step of same-address L2 atomic
// serialization. Flags are monotonic (t+1); max inter-block skew is 1 step,
// so `>= target` is exact and buffers can't be overwritten early (a block
// reaches step t+2's writes only after observing every flag >= t+1, which
// implies every block finished reading buffer t&1).
__global__ __launch_bounds__(TPB, 1) void k_seq(const float* __restrict__ Whh,
                                                const float* __restrict__ G)
{
    const int b = blockIdx.x;
    const int tid = threadIdx.x;
    const int warp = tid >> 5, lane = tid & 31;

    __shared__ float hsh[HID];

    const int u = b * JPB + warp;    // hidden unit owned by this warp
    float creg = 0.f;                // cell state (lane 0 meaningful)

    int rows[4];
    float w[4][32];
    #pragma unroll
    for (int gate = 0; gate < 4; gate++) {
        rows[gate] = (gate << 10) + u;
        const float* wrow = Whh + (size_t)rows[gate] * HID + lane;
        #pragma unroll
        for (int i = 0; i < 32; i++) w[gate][i] = wrow[i * 32];
    }

    for (int t = 0; t < SEQ; t++) {
        // prefetch precomputed gate terms for this step (independent of h)
        float g0 = 0.f, g1 = 0.f, g2 = 0.f, g3 = 0.f;
        if (lane == 0) {
            const float* gt = G + (size_t)t * G4;
            g0 = __ldcg(gt + rows[0]);
            g1 = __ldcg(gt + rows[1]);
            g2 = __ldcg(gt + rows[2]);
            g3 = __ldcg(gt + rows[3]);
        }

        // load h (written by all blocks last step) — bypass L1
        const float* hg = g_st.h[t & 1];
        #pragma unroll
        for (int i = 0; i < HID / TPB; i++)
            hsh[tid + i * TPB] = __ldcg(hg + tid + i * TPB);
        __syncthreads();

        float hreg[32];
        #pragma unroll
        for (int i = 0; i < 32; i++) hreg[i] = hsh[i * 32 + lane];

        float a0 = 0.f, a1 = 0.f, a2 = 0.f, a3 = 0.f;
        #pragma unroll
        for (int i = 0; i < 32; i++) {
            a0 += w[0][i] * hreg[i];
            a1 += w[1][i] * hreg[i];
            a2 += w[2][i] * hreg[i];
            a3 += w[3][i] * hreg[i];
        }
        #pragma unroll
        for (int off = 16; off; off >>= 1) {
            a0 += __shfl_xor_sync(0xffffffffu, a0, off);
            a1 += __shfl_xor_sync(0xffffffffu, a1, off);
            a2 += __shfl_xor_sync(0xffffffffu, a2, off);
            a3 += __shfl_xor_sync(0xffffffffu, a3, off);
        }

        if (lane == 0) {
            float iv = a0 + g0;              // gate 0: input
            float fv = a1 + g1;              // gate 1: forget
            float gv = a2 + g2;              // gate 2: cell
            float ov = a3 + g3;              // gate 3: output
            float is = 1.f / (1.f + __expf(-iv));
            float fs = 1.f / (1.f + __expf(-fv));
            float os = 1.f / (1.f + __expf(-ov));
            float tg = 1.f - 2.f / (__expf(2.f * gv) + 1.f);   // tanh(gv)
            float cn = fs * creg + is * tg;
            creg = cn;
            float tc = 1.f - 2.f / (__expf(2.f * cn) + 1.f);   // tanh(cn)
            g_st.h[(t + 1) & 1][u] = os * tc;
        }
        __syncthreads();   // all h-stores of this block issued before arrival

        // grid barrier: distinct-address flag arrival + single-spinner sweep
        if (tid == 0) {
            const unsigned target = (unsigned)t + 1u;
            __threadfence();   // cumulative release of this block's h-stores
            asm volatile("st.global.cg.u32 [%0], %1;"
                         :: "l"(g_flags + b), "r"(target) : "memory");
            unsigned done = 0u;            // bit per uint4 group (32 groups)
            unsigned sweeps = 0u;
            while (done != 0xFFFFFFFFu) {
                #pragma unroll
                for (int gi = 0; gi < NB / 4; gi++) {
                    if (!(done & (1u << gi))) {
                        unsigned f0, f1, f2, f3;
                        asm volatile("ld.global.cg.v4.u32 {%0,%1,%2,%3}, [%4];"
                                     : "=r"(f0), "=r"(f1), "=r"(f2), "=r"(f3)
                                     : "l"((const unsigned*)g_flags + gi * 4));
                        if (f0 >= target && f1 >= target && f2 >= target && f3 >= target)
                            done |= 1u << gi;
                    }
                }
                if (++sweeps > SPIN_SWEEP_LIMIT) __trap();  // hang -> fast fail
            }
            __threadfence();   // acquire side (same placement as proven R5)
        }
        __syncthreads();
    }
}

// out[l] = dot(out_W[l], h_final) + out_b[l]; final h lives in buffer 0 (SEQ even)
__global__ void k_out(const float* __restrict__ outW, const float* __restrict__ outB,
                      float* __restrict__ out)
{
    int warp = threadIdx.x >> 5, lane = threadIdx.x & 31;
    if (warp < LABELS) {
        const float* wr = outW + (size_t)warp * HID;
        const float* h = g_st.h[0];
        float s = 0.f;
        for (int k = lane; k < HID; k += 32) s += wr[k] * h[k];
        #pragma unroll
        for (int off = 16; off; off >>= 1) s += __shfl_xor_sync(0xffffffffu, s, off);
        if (lane == 0) out[warp] = s + outB[warp];
    }
}

// ---------------- launch ----------------
// Launch order keeps k_seq as app launch #4 (where ncu's capture lands):
// prep(1), GEMM-C(2), GEMM-G(3), k_seq(4), k_out(5).
extern "C" void kernel_launch(void* const* d_in, const int* in_sizes, int n_in,
                              void* d_out, int out_size)
{
    const int*   sids  = (const int*)  d_in[0];
    const int*   eids  = (const int*)  d_in[1];
    const float* wemb  = (const float*)d_in[2];
    const float* eemb  = (const float*)d_in[3];
    // d_in[4] attn_W, d_in[5] attn_b: mathematically dead (softmax of 1 logit == 1)
    const float* combW = (const float*)d_in[6];
    const float* combB = (const float*)d_in[7];
    const float* Wih   = (const float*)d_in[8];
    const float* Whh   = (const float*)d_in[9];
    const float* bih   = (const float*)d_in[10];
    const float* bhh   = (const float*)d_in[11];
    const float* outW  = (const float*)d_in[12];
    const float* outB  = (const float*)d_in[13];
    float* out = (float*)d_out;

    void *pC = 0, *pG = 0, *pc2 = 0;
    cudaGetSymbolAddress(&pC,  g_C);
    cudaGetSymbolAddress(&pG,  g_G);
    cudaGetSymbolAddress(&pc2, g_const2);

    k_prep<<<NB, TPB>>>(eids, eemb, combW, combB);

    // C = relu(gather(word_emb, sids) @ Wx^T + const2), Wx = comb_W[:, 0:EMB]
    dim3 gridC(EMB / 128, SEQ / 128);
    sgemm_nt<<<gridC, 256>>>(wemb, EMB, sids, combW, 2 * EMB,
                             (const float*)pc2, (const float*)0,
                             (float*)pC, EMB, EMB, 1);

    // G = C @ W_ih^T + b_ih + b_hh   (both biases folded into epilogue)
    dim3 gridG(G4 / 128, SEQ / 128);
    sgemm_nt<<<gridG, 256>>>((const float*)pC, EMB, (const int*)0, Wih, EMB,
                             bih, bhh, (float*)pG, G4, EMB, 0);

    k_seq<<<NB, TPB>>>(Whh, (const float*)pG);
    k_out<<<1, 256>>>(outW, outB, out);
}

// round 17
// speedup vs baseline: 3.7124x; 3.7124x over previous
#include <cuda_runtime.h>
#include <math.h>

#define EMB 1024
#define HID 1024
#define SEQ 2048
#define NEMO 16
#define LABELS 7
#define G4 (4*HID)

#define NB 128        // blocks in sequential kernel (<= 148 SMs -> co-resident)
#define JPB (HID/NB)  // 8 hidden units per block (= warps per block)
#define TPB 256

// ---------------- static device scratch (no allocations allowed) ----------------
// Barrier = single counter + atomicAdd + single volatile spinner per block.
// PROVEN (R5/R12/R15). R16 falsified the "atomic serialization" theory and
// confirmed the real rule: at most ONE poller per block on ONE line — multi-
// line polling saturates the L2 slices those lines hash to (R6-8, R16).
struct SeqState {
    unsigned counter;
    unsigned pad[31];
    float __align__(16) h[2][HID];   // double-buffered hidden state (16B for v4 loads)
};

__device__ float g_C [SEQ * EMB];       // relu(comb) per step       (8 MB)
__device__ float g_G [SEQ * G4];        // W_ih @ C + b_ih + b_hh    (32 MB)
__device__ float g_const2[EMB];         // We @ emoji_ave + comb_b
__device__ SeqState g_st;

// ---------------- f32x2 packed helpers ----------------
__device__ __forceinline__ unsigned long long pk2(float x, float y) {
    unsigned long long r;
    asm("mov.b64 %0, {%1, %2};" : "=l"(r) : "f"(x), "f"(y));
    return r;
}
__device__ __forceinline__ void upk2(float& x, float& y, unsigned long long v) {
    asm("mov.b64 {%0, %1}, %2;" : "=f"(x), "=f"(y) : "l"(v));
}
__device__ __forceinline__ unsigned long long fma2(unsigned long long a,
                                                   unsigned long long b,
                                                   unsigned long long c) {
    unsigned long long d;
    asm("fma.rn.f32x2 %0, %1, %2, %3;" : "=l"(d) : "l"(a), "l"(b), "l"(c));
    return d;
}

// ---------------- fused prep kernel (launch #1) ----------------
__global__ __launch_bounds__(TPB) void k_prep(const int* __restrict__ eids,
                                              const float* __restrict__ eemb,
                                              const float* __restrict__ combW,
                                              const float* __restrict__ combB)
{
    __shared__ float esh[EMB];
    const int tid = threadIdx.x;
    const int warp = tid >> 5, lane = tid & 31;

    for (int e = tid; e < EMB; e += TPB) {
        float s = 0.f;
        #pragma unroll
        for (int n = 0; n < NEMO; n++)
            s += eemb[(size_t)eids[n] * EMB + e];
        esh[e] = s * (1.0f / NEMO);
    }

    if (blockIdx.x == 0) {
        if (tid == 0) g_st.counter = 0u;
        float* h = &g_st.h[0][0];
        for (int i = tid; i < 2 * HID; i += TPB) h[i] = 0.f;
    }
    __syncthreads();

    // const2[row] = dot(comb_W[row, EMB:2EMB], emoji_ave) + comb_b[row]
    int row = blockIdx.x * 8 + warp;
    const float* wr = combW + (size_t)row * (2 * EMB) + EMB;
    float s = 0.f;
    for (int k = lane; k < EMB; k += 32) s += wr[k] * esh[k];
    #pragma unroll
    for (int off = 16; off; off >>= 1) s += __shfl_xor_sync(0xffffffffu, s, off);
    if (lane == 0) g_const2[row] = s + combB[row];
}

// ---------------- SIMT SGEMM:  C[M,N] = A[M,K] @ B[N,K]^T + bias(+bias2) (opt relu) ----
__global__ __launch_bounds__(256) void sgemm_nt(
    const float* __restrict__ A, int lda, const int* __restrict__ ids,
    const float* __restrict__ B, int ldb,
    const float* __restrict__ bias, const float* __restrict__ bias2,
    float* __restrict__ Cc, int ldc,
    int K, int relu)
{
    __shared__ float As[2][16][128];
    __shared__ float Bs[2][16][128];

    const int tid = threadIdx.x;
    const int m0 = blockIdx.y * 128;
    const int n0 = blockIdx.x * 128;
    const int tx = tid & 15;
    const int ty = tid >> 4;
    const int lr = tid >> 2;
    const int lq = tid & 3;

    const float* aptr[2];
    const float* bptr[2];
    #pragma unroll
    for (int s = 0; s < 2; s++) {
        int r = lr + s * 64;
        int am = ids ? ids[m0 + r] : (m0 + r);
        aptr[s] = A + (size_t)am * lda + lq * 4;
        bptr[s] = B + (size_t)(n0 + r) * ldb + lq * 4;
    }

    float4 ra[2], rb[2];

    float acc[8][8];
    #pragma unroll
    for (int r = 0; r < 8; r++)
        #pragma unroll
        for (int c = 0; c < 8; c++) acc[r][c] = 0.f;

    #pragma unroll
    for (int s = 0; s < 2; s++) { ra[s] = *(const float4*)(aptr[s]); rb[s] = *(const float4*)(bptr[s]); }
    #pragma unroll
    for (int s = 0; s < 2; s++) {
        int r = lr + s * 64;
        As[0][lq*4+0][r] = ra[s].x; As[0][lq*4+1][r] = ra[s].y;
        As[0][lq*4+2][r] = ra[s].z; As[0][lq*4+3][r] = ra[s].w;
        Bs[0][lq*4+0][r] = rb[s].x; Bs[0][lq*4+1][r] = rb[s].y;
        Bs[0][lq*4+2][r] = rb[s].z; Bs[0][lq*4+3][r] = rb[s].w;
    }
    __syncthreads();

    int buf = 0;
    for (int k0 = 16; k0 <= K; k0 += 16) {
        if (k0 < K) {
            #pragma unroll
            for (int s = 0; s < 2; s++) {
                ra[s] = *(const float4*)(aptr[s] + k0);
                rb[s] = *(const float4*)(bptr[s] + k0);
            }
        }

        #pragma unroll
        for (int k = 0; k < 16; k++) {
            float4 a0 = *(const float4*)&As[buf][k][ty * 8];
            float4 a1 = *(const float4*)&As[buf][k][ty * 8 + 4];
            float4 b0 = *(const float4*)&Bs[buf][k][tx * 8];
            float4 b1 = *(const float4*)&Bs[buf][k][tx * 8 + 4];
            float a[8] = {a0.x, a0.y, a0.z, a0.w, a1.x, a1.y, a1.z, a1.w};
            float b[8] = {b0.x, b0.y, b0.z, b0.w, b1.x, b1.y, b1.z, b1.w};
            #pragma unroll
            for (int r = 0; r < 8; r++)
                #pragma unroll
                for (int c = 0; c < 8; c++)
                    acc[r][c] += a[r] * b[c];
        }

        if (k0 < K) {
            int nb = buf ^ 1;
            #pragma unroll
            for (int s = 0; s < 2; s++) {
                int r = lr + s * 64;
                As[nb][lq*4+0][r] = ra[s].x; As[nb][lq*4+1][r] = ra[s].y;
                As[nb][lq*4+2][r] = ra[s].z; As[nb][lq*4+3][r] = ra[s].w;
                Bs[nb][lq*4+0][r] = rb[s].x; Bs[nb][lq*4+1][r] = rb[s].y;
                Bs[nb][lq*4+2][r] = rb[s].z; Bs[nb][lq*4+3][r] = rb[s].w;
            }
            __syncthreads();
            buf = nb;
        }
    }

    #pragma unroll
    for (int r = 0; r < 8; r++) {
        int m = m0 + ty * 8 + r;
        float* cp = Cc + (size_t)m * ldc + n0 + tx * 8;
        #pragma unroll
        for (int c = 0; c < 8; c++) {
            int n = n0 + tx * 8 + c;
            float v = acc[r][c] + bias[n];
            if (bias2) v += bias2[n];
            if (relu) v = fmaxf(v, 0.f);
            cp[c] = v;
        }
    }
}

// ---------------- persistent sequential LSTM kernel ----------------
// 128 blocks x 256 threads (8 warps). Warp-per-unit: warp w owns hidden unit
// u = b*8+w (all 4 gate rows). NEW data layout: lane L owns h[L*32..L*32+31]
// (contiguous) so h/weight pairs feed dual-issue fma.rn.f32x2 (64 packed FMA
// + 16 LDS.64 per thread instead of 128 FMA + 32 LDS). Activations spread
// over lanes 0-3 (parallel MUFU), shfl-combined on lane 0. Grid barrier
// VERBATIM R15/R5 (single counter, atomicAdd arrival, tid0-only volatile
// spin on one line, fences both sides) — proven 3x; R16 proved multi-line
// polling pathologically saturates L2 slices. Do not touch.
__global__ __launch_bounds__(TPB, 1) void k_seq(const float* __restrict__ Whh,
                                                const float* __restrict__ G)
{
    const int b = blockIdx.x;
    const int tid = threadIdx.x;
    const int warp = tid >> 5, lane = tid & 31;

    // pad-34 layout: h element k lives at (k>>5)*34 + (k&31); for 64-bit LDS
    // reads at lane*34+2j the bank pairs are distinct across a 16-lane phase.
    __shared__ float hsh[32 * 34];

    const int u = b * JPB + warp;    // hidden unit owned by this warp
    float creg = 0.f;                // cell state (lane 0 meaningful)

    // packed weights: w2[gate][j] = (Whh[row, lane*32+2j], Whh[row, lane*32+2j+1])
    unsigned long long w2[4][16];
    #pragma unroll
    for (int gate = 0; gate < 4; gate++) {
        int row = (gate << 10) + u;
        const float2* wp = (const float2*)(Whh + (size_t)row * HID + lane * 32);
        #pragma unroll
        for (int j = 0; j < 16; j++) {
            float2 t = __ldg(wp + j);
            w2[gate][j] = pk2(t.x, t.y);
        }
    }

    const float4* hbuf4[2] = { (const float4*)g_st.h[0], (const float4*)g_st.h[1] };

    for (int t = 0; t < SEQ; t++) {
        // prefetch G terms: lane g (0..3) loads its own gate's value
        float gl = 0.f;
        if (lane < 4)
            gl = __ldcg(G + (size_t)t * G4 + (lane << 10) + u);

        // h fill: one float4 ldcg per thread -> padded smem (two STS.64)
        float4 F = __ldcg(hbuf4[t & 1] + tid);
        int base = (tid >> 3) * 34 + ((tid & 7) << 2);
        *(float2*)&hsh[base]     = make_float2(F.x, F.y);
        *(float2*)&hsh[base + 2] = make_float2(F.z, F.w);
        __syncthreads();

        // packed matvec: 16 LDS.64 + 64 fma.f32x2 per thread
        unsigned long long acc0 = pk2(0.f, 0.f), acc1 = acc0, acc2 = acc0, acc3 = acc0;
        const int hb = lane * 34;
        #pragma unroll
        for (int j = 0; j < 16; j++) {
            float2 hv = *(const float2*)&hsh[hb + 2 * j];
            unsigned long long h2 = pk2(hv.x, hv.y);
            acc0 = fma2(w2[0][j], h2, acc0);
            acc1 = fma2(w2[1][j], h2, acc1);
            acc2 = fma2(w2[2][j], h2, acc2);
            acc3 = fma2(w2[3][j], h2, acc3);
        }
        float a0, a1, a2, a3, lo, hi;
        upk2(lo, hi, acc0); a0 = lo + hi;
        upk2(lo, hi, acc1); a1 = lo + hi;
        upk2(lo, hi, acc2); a2 = lo + hi;
        upk2(lo, hi, acc3); a3 = lo + hi;
        #pragma unroll
        for (int off = 16; off; off >>= 1) {
            a0 += __shfl_xor_sync(0xffffffffu, a0, off);
            a1 += __shfl_xor_sync(0xffffffffu, a1, off);
            a2 += __shfl_xor_sync(0xffffffffu, a2, off);
            a3 += __shfl_xor_sync(0xffffffffu, a3, off);
        }

        // parallel activations: lane g applies its gate's nonlinearity
        float av  = (lane == 0) ? a0 : (lane == 1) ? a1 : (lane == 2) ? a2 : a3;
        float pre = av + gl;
        float act = (lane == 2) ? (1.f - 2.f / (__expf(2.f * pre) + 1.f))   // tanh(g)
                                : (1.f / (1.f + __expf(-pre)));             // sigmoid
        float fs = __shfl_sync(0xffffffffu, act, 1);
        float tg = __shfl_sync(0xffffffffu, act, 2);
        float os = __shfl_sync(0xffffffffu, act, 3);
        if (lane == 0) {
            float cn = fs * creg + act * tg;   // act = sigmoid(i) on lane 0
            creg = cn;
            float tc = 1.f - 2.f / (__expf(2.f * cn) + 1.f);
            g_st.h[(t + 1) & 1][u] = os * tc;
        }
        __syncthreads();   // all h-stores of this block issued before arrival

        // grid barrier (release h-writes, acquire others') — VERBATIM R5/R15
        if (tid == 0) {
            __threadfence();
            atomicAdd(&g_st.counter, 1u);
            unsigned target = (unsigned)(t + 1) * NB;
            while (*((volatile unsigned*)&g_st.counter) < target) { }
            __threadfence();
        }
        __syncthreads();
    }
}

// out[l] = dot(out_W[l], h_final) + out_b[l]; final h lives in buffer 0 (SEQ even)
__global__ void k_out(const float* __restrict__ outW, const float* __restrict__ outB,
                      float* __restrict__ out)
{
    int warp = threadIdx.x >> 5, lane = threadIdx.x & 31;
    if (warp < LABELS) {
        const float* wr = outW + (size_t)warp * HID;
        const float* h = g_st.h[0];
        float s = 0.f;
        for (int k = lane; k < HID; k += 32) s += wr[k] * h[k];
        #pragma unroll
        for (int off = 16; off; off >>= 1) s += __shfl_xor_sync(0xffffffffu, s, off);
        if (lane == 0) out[warp] = s + outB[warp];
    }
}

// ---------------- launch ----------------
// Launch order keeps k_seq as app launch #4 (where ncu's capture lands):
// prep(1), GEMM-C(2), GEMM-G(3), k_seq(4), k_out(5).
extern "C" void kernel_launch(void* const* d_in, const int* in_sizes, int n_in,
                              void* d_out, int out_size)
{
    const int*   sids  = (const int*)  d_in[0];
    const int*   eids  = (const int*)  d_in[1];
    const float* wemb  = (const float*)d_in[2];
    const float* eemb  = (const float*)d_in[3];
    // d_in[4] attn_W, d_in[5] attn_b: mathematically dead (softmax of 1 logit == 1)
    const float* combW = (const float*)d_in[6];
    const float* combB = (const float*)d_in[7];
    const float* Wih   = (const float*)d_in[8];
    const float* Whh   = (const float*)d_in[9];
    const float* bih   = (const float*)d_in[10];
    const float* bhh   = (const float*)d_in[11];
    const float* outW  = (const float*)d_in[12];
    const float* outB  = (const float*)d_in[13];
    float* out = (float*)d_out;

    void *pC = 0, *pG = 0, *pc2 = 0;
    cudaGetSymbolAddress(&pC,  g_C);
    cudaGetSymbolAddress(&pG,  g_G);
    cudaGetSymbolAddress(&pc2, g_const2);

    k_prep<<<NB, TPB>>>(eids, eemb, combW, combB);

    // C = relu(gather(word_emb, sids) @ Wx^T + const2), Wx = comb_W[:, 0:EMB]
    dim3 gridC(EMB / 128, SEQ / 128);
    sgemm_nt<<<gridC, 256>>>(wemb, EMB, sids, combW, 2 * EMB,
                             (const float*)pc2, (const float*)0,
                             (float*)pC, EMB, EMB, 1);

    // G = C @ W_ih^T + b_ih + b_hh   (both biases folded into epilogue)
    dim3 gridG(G4 / 128, SEQ / 128);
    sgemm_nt<<<gridG, 256>>>((const float*)pC, EMB, (const int*)0, Wih, EMB,
                             bih, bhh, (float*)pG, G4, EMB, 0);

    k_seq<<<NB, TPB>>>(Whh, (const float*)pG);
    k_out<<<1, 256>>>(outW, outB, out);
}